// round 15
// baseline (speedup 1.0000x reference)
#include <cuda_runtime.h>
#include <math.h>

#define T_STEPS 256
#define BATCH   2048
#define DIN     128
#define NQ      16
#define NC      64   // 4 gates * 16 qubits

// 134 MB scratch for the precomputed x-part of the pre-activations.
// zx[t*BATCH*NC + b*NC + c] = sum_{d<128} x[t,b,d] * W[c,d]
__device__ float g_zx[(size_t)T_STEPS * BATCH * NC];

// ---------------------------------------------------------------------------
// Packed fp32x2 helpers (sm_100+ PTX; ptxas will not auto-fuse these)
// ---------------------------------------------------------------------------
__device__ __forceinline__ unsigned long long ffma2(
    unsigned long long a, unsigned long long b, unsigned long long c) {
    unsigned long long d;
    asm("fma.rn.f32x2 %0, %1, %2, %3;" : "=l"(d) : "l"(a), "l"(b), "l"(c));
    return d;
}
__device__ __forceinline__ unsigned long long pack2(float lo, float hi) {
    unsigned long long d;
    asm("mov.b64 %0, {%1, %2};" : "=l"(d) : "f"(lo), "f"(hi));
    return d;
}
__device__ __forceinline__ float2 unpack2(unsigned long long v) {
    float2 r;
    asm("mov.b64 {%0, %1}, %2;" : "=f"(r.x), "=f"(r.y) : "l"(v));
    return r;
}
__device__ __forceinline__ float tanh_apx(float x) {
    float r;
    asm("tanh.approx.f32 %0, %1;" : "=f"(r) : "f"(x));
    return r;
}

// ---------------------------------------------------------------------------
// Kernel A: GEMM. M = T*B = 524288 rows, N = 64, K = 128 (4 chunks of 32).
// Tile 128 rows x 64 cols per block of 256 threads; thread tile 8x4.
// X stored k-major (adjacent rows = native f32x2 pairs), W stored duplicated
// (w,w) pairs so the inner loop is 4x LDS.128 + 16x FFMA2 with zero movs.
// ---------------------------------------------------------------------------
#define KCH 32
__global__ __launch_bounds__(256) void qlstm_gemm_x(
    const float* __restrict__ X,   // [M, 128]
    const float* __restrict__ W)   // [64, 144] (only d<128 used here)
{
    __shared__ float Xt[KCH][128];    // [k][row]
    __shared__ float Wt2[KCH][128];   // [k][2*col] duplicated pairs

    const int tid = threadIdx.x;
    const int tx = tid & 15;          // col group: cols tx*4 .. tx*4+3
    const int ty = tid >> 4;          // row group: rows ty*8 .. ty*8+7
    const size_t row0 = (size_t)blockIdx.x * 128;

    unsigned long long acc[4][4];     // [row-pair][col], packed over 2 rows
#pragma unroll
    for (int rp = 0; rp < 4; rp++)
#pragma unroll
        for (int c = 0; c < 4; c++) acc[rp][c] = 0ull;

    // loader mappings
    const int xrow = tid >> 1;              // 0..127 (2 threads per row)
    const int xk   = (tid & 1) * 16;        // k-half base
    const int wcol = tid >> 2;              // 0..63 (4 threads per col)
    const int wk   = (tid & 3) * 8;         // k-eighth base (2 float4)

#pragma unroll
    for (int kc = 0; kc < 4; kc++) {
        // --- load X tile k-major: Xt[k][row] ---
        {
            const float* xp = &X[(row0 + xrow) * DIN + kc * KCH + xk];
#pragma unroll
            for (int i = 0; i < 4; i++) {
                float4 v = *reinterpret_cast<const float4*>(xp + i * 4);
                const int k4 = xk + i * 4;
                Xt[k4 + 0][xrow] = v.x;
                Xt[k4 + 1][xrow] = v.y;
                Xt[k4 + 2][xrow] = v.z;
                Xt[k4 + 3][xrow] = v.w;
            }
        }
        // --- load W tile k-major, duplicated: Wt2[k][2c],[2c+1] = W[c][k] ---
        {
            const float* wp = &W[wcol * 144 + kc * KCH + wk];
#pragma unroll
            for (int i = 0; i < 2; i++) {
                float4 v = *reinterpret_cast<const float4*>(wp + i * 4);
                const int k4 = wk + i * 4;
                *reinterpret_cast<unsigned long long*>(&Wt2[k4 + 0][2 * wcol]) = pack2(v.x, v.x);
                *reinterpret_cast<unsigned long long*>(&Wt2[k4 + 1][2 * wcol]) = pack2(v.y, v.y);
                *reinterpret_cast<unsigned long long*>(&Wt2[k4 + 2][2 * wcol]) = pack2(v.z, v.z);
                *reinterpret_cast<unsigned long long*>(&Wt2[k4 + 3][2 * wcol]) = pack2(v.w, v.w);
            }
        }
        __syncthreads();

#pragma unroll
        for (int k = 0; k < KCH; k++) {
            ulonglong2 aa0 = *reinterpret_cast<ulonglong2*>(&Xt[k][ty * 8]);
            ulonglong2 aa1 = *reinterpret_cast<ulonglong2*>(&Xt[k][ty * 8 + 4]);
            ulonglong2 bb0 = *reinterpret_cast<ulonglong2*>(&Wt2[k][tx * 8]);
            ulonglong2 bb1 = *reinterpret_cast<ulonglong2*>(&Wt2[k][tx * 8 + 4]);
            acc[0][0] = ffma2(aa0.x, bb0.x, acc[0][0]);
            acc[0][1] = ffma2(aa0.x, bb0.y, acc[0][1]);
            acc[0][2] = ffma2(aa0.x, bb1.x, acc[0][2]);
            acc[0][3] = ffma2(aa0.x, bb1.y, acc[0][3]);
            acc[1][0] = ffma2(aa0.y, bb0.x, acc[1][0]);
            acc[1][1] = ffma2(aa0.y, bb0.y, acc[1][1]);
            acc[1][2] = ffma2(aa0.y, bb1.x, acc[1][2]);
            acc[1][3] = ffma2(aa0.y, bb1.y, acc[1][3]);
            acc[2][0] = ffma2(aa1.x, bb0.x, acc[2][0]);
            acc[2][1] = ffma2(aa1.x, bb0.y, acc[2][1]);
            acc[2][2] = ffma2(aa1.x, bb1.x, acc[2][2]);
            acc[2][3] = ffma2(aa1.x, bb1.y, acc[2][3]);
            acc[3][0] = ffma2(aa1.y, bb0.x, acc[3][0]);
            acc[3][1] = ffma2(aa1.y, bb0.y, acc[3][1]);
            acc[3][2] = ffma2(aa1.y, bb1.x, acc[3][2]);
            acc[3][3] = ffma2(aa1.y, bb1.y, acc[3][3]);
        }
        __syncthreads();
    }

    // --- store: each acc[rp][c] holds (row even, row odd) for col tx*4+c ---
#pragma unroll
    for (int rp = 0; rp < 4; rp++) {
        float2 p0 = unpack2(acc[rp][0]);
        float2 p1 = unpack2(acc[rp][1]);
        float2 p2 = unpack2(acc[rp][2]);
        float2 p3 = unpack2(acc[rp][3]);
        const size_t re = row0 + ty * 8 + 2 * rp;
        *reinterpret_cast<float4*>(&g_zx[re * NC + tx * 4]) =
            make_float4(p0.x, p1.x, p2.x, p3.x);
        *reinterpret_cast<float4*>(&g_zx[(re + 1) * NC + tx * 4]) =
            make_float4(p0.y, p1.y, p2.y, p3.y);
    }
}

// ---------------------------------------------------------------------------
// Kernel B: sequential recurrence. One warp per block, one block per batch row.
// Lanes 0-15  : gates 0 (forget) and 1 (input), qubit n = lane
// Lanes 16-31 : gates 2 (update) and 3 (output), qubit n = lane-16
// h broadcast via double-buffered smem (kills 16 of 26 SHFLs per step);
// sigmoid/tanh via hardware tanh.approx (1 MUFU each).
// ---------------------------------------------------------------------------
__global__ __launch_bounds__(32) void qlstm_recur(
    const float* __restrict__ W,      // [4,16,144]
    const float* __restrict__ bias,   // [4,16]
    const float* __restrict__ theta,  // [4,16]
    float* __restrict__ out)          // outputs [T,B,16] ++ hx [B,16] ++ cx [B,16]
{
    __shared__ float h_s[2][16];

    const int gw   = blockIdx.x;          // batch row
    const int lane = threadIdx.x;

    const int half = lane >> 4;
    const int n    = lane & 15;
    const int cA   = 32 * half + n;       // column of gate 2*half
    const int cB   = cA + 16;             // column of gate 2*half+1

    // recurrent weights, pre-packed as f32x2 pairs over j
    unsigned long long whA2[8], whB2[8];
#pragma unroll
    for (int j2 = 0; j2 < 8; j2++) {
        whA2[j2] = pack2(W[cA * 144 + 128 + 2 * j2], W[cA * 144 + 128 + 2 * j2 + 1]);
        whB2[j2] = pack2(W[cB * 144 + 128 + 2 * j2], W[cB * 144 + 128 + 2 * j2 + 1]);
    }
    const float ctA = bias[cA] + theta[cA];
    const float ctB = bias[cB] + theta[cB];

    // branch-free nonlinearity constants:
    //   half0 v0: sigmoid(x) = 0.5*tanh(0.5x)+0.5 ; half1 v0: tanh(x)
    const float s0 = half ? 1.0f : 0.5f;   // pre-scale (also the multiplier)
    const float b0 = half ? 0.0f : 0.5f;   // offset

    float h = 0.f, c = 0.f;
    if (lane < 16) h_s[0][n] = 0.f;
    __syncthreads();

    const float* zp = g_zx + (size_t)gw * NC;
    const size_t zstride = (size_t)BATCH * NC;

    // prefetch step 0
    float z0n = zp[cA];
    float z1n = zp[cB];

    float* outp = out + (size_t)gw * 16 + n;

    for (int t = 0; t < T_STEPS; t++) {
        // dot: h . Wh via broadcast LDS.64 + packed FFMA2
        unsigned long long accA = pack2(z0n + ctA, 0.f);
        unsigned long long accB = pack2(z1n + ctB, 0.f);
        const unsigned long long* hp =
            reinterpret_cast<const unsigned long long*>(h_s[t & 1]);
#pragma unroll
        for (int j2 = 0; j2 < 8; j2++) {
            unsigned long long hv = hp[j2];
            accA = ffma2(hv, whA2[j2], accA);
            accB = ffma2(hv, whB2[j2], accB);
        }
        float2 rA = unpack2(accA);
        float2 rB = unpack2(accB);
        float a0 = rA.x + rA.y;
        float a1 = rB.x + rB.y;

        // prefetch next step's pre-activations
        if (t + 1 < T_STEPS) {
            const float* q = zp + (size_t)(t + 1) * zstride;
            z0n = q[cA];
            z1n = q[cB];
        }

        a0 = __cosf(a0);
        a1 = __cosf(a1);

        // inclusive prefix product (cumprod over qubits) within each half-warp
#pragma unroll
        for (int d = 1; d < 16; d <<= 1) {
            float p0 = __shfl_up_sync(0xffffffffu, a0, d, 16);
            float p1 = __shfl_up_sync(0xffffffffu, a1, d, 16);
            if (n >= d) { a0 *= p0; a1 *= p1; }
        }

        // gate nonlinearities (1 MUFU each)
        float v0 = fmaf(s0, tanh_apx(a0 * s0), b0);               // sig | tanh
        float v1 = fmaf(0.5f, tanh_apx(a1 * 0.5f), 0.5f);         // sigmoid

        // exchange with partner half-warp lane
        float pv0 = __shfl_sync(0xffffffffu, v0, lane ^ 16);
        float pv1 = __shfl_sync(0xffffffffu, v1, lane ^ 16);

        float f_ = half ? pv0 : v0;
        float i_ = half ? pv1 : v1;
        float g_ = half ? v0  : pv0;
        float o_ = half ? v1  : pv1;

        c = fmaf(f_, c, i_ * g_);
        h = o_ * tanh_apx(c);

        if (half == 0) {
            outp[(size_t)t * (BATCH * 16)] = h;
            h_s[(t + 1) & 1][n] = h;       // publish h for next step's dot
        }
        __syncthreads();                    // BAR nw=1: ~3 cyc, drains STS
    }

    if (half == 0) {
        const size_t base = (size_t)T_STEPS * BATCH * 16;
        out[base + (size_t)gw * 16 + n] = h;                       // hx
        out[base + (size_t)BATCH * 16 + (size_t)gw * 16 + n] = c;  // cx
    }
}

// ---------------------------------------------------------------------------
extern "C" void kernel_launch(void* const* d_in, const int* in_sizes, int n_in,
                              void* d_out, int out_size) {
    const float* X     = (const float*)d_in[0];   // [T,B,128]
    const float* W     = (const float*)d_in[1];   // [4,16,144]
    const float* bias  = (const float*)d_in[2];   // [4,16]
    const float* theta = (const float*)d_in[3];   // [4,16]
    float* out = (float*)d_out;

    // Kernel A: 524288 rows / 128 per block
    qlstm_gemm_x<<<(T_STEPS * BATCH) / 128, 256>>>(X, W);

    // Kernel B: one warp per batch row, one block per warp (load balance)
    qlstm_recur<<<BATCH, 32>>>(W, bias, theta, out);
}

// round 16
// speedup vs baseline: 1.0020x; 1.0020x over previous
#include <cuda_runtime.h>
#include <math.h>

#define T_STEPS 256
#define BATCH   2048
#define DIN     128
#define NQ      16
#define NC      64   // 4 gates * 16 qubits

// 134 MB scratch for the precomputed x-part of the pre-activations.
// zx[t*BATCH*NC + b*NC + c] = sum_{d<128} x[t,b,d] * W[c,d]
__device__ float g_zx[(size_t)T_STEPS * BATCH * NC];

// ---------------------------------------------------------------------------
// Packed fp32x2 helpers (sm_100+ PTX; ptxas will not auto-fuse these)
// ---------------------------------------------------------------------------
__device__ __forceinline__ unsigned long long ffma2(
    unsigned long long a, unsigned long long b, unsigned long long c) {
    unsigned long long d;
    asm("fma.rn.f32x2 %0, %1, %2, %3;" : "=l"(d) : "l"(a), "l"(b), "l"(c));
    return d;
}
__device__ __forceinline__ unsigned long long pack2(float lo, float hi) {
    unsigned long long d;
    asm("mov.b64 %0, {%1, %2};" : "=l"(d) : "f"(lo), "f"(hi));
    return d;
}
__device__ __forceinline__ float2 unpack2(unsigned long long v) {
    float2 r;
    asm("mov.b64 {%0, %1}, %2;" : "=f"(r.x), "=f"(r.y) : "l"(v));
    return r;
}
__device__ __forceinline__ float tanh_apx(float x) {
    float r;
    asm("tanh.approx.f32 %0, %1;" : "=f"(r) : "f"(x));
    return r;
}

// ---------------------------------------------------------------------------
// Kernel A: GEMM. M = T*B = 524288 rows, N = 64, K = 128 (4 chunks of 32).
// Tile 128 rows x 64 cols per block of 256 threads; thread tile 8x4.
// X stored k-major (adjacent rows = native f32x2 pairs), W stored duplicated
// (w,w) pairs so the inner loop is 4x LDS.128 + 16x FFMA2 with zero movs.
// ---------------------------------------------------------------------------
#define KCH 32
__global__ __launch_bounds__(256) void qlstm_gemm_x(
    const float* __restrict__ X,   // [M, 128]
    const float* __restrict__ W)   // [64, 144] (only d<128 used here)
{
    __shared__ float Xt[KCH][128];    // [k][row]
    __shared__ float Wt2[KCH][128];   // [k][2*col] duplicated pairs

    const int tid = threadIdx.x;
    const int tx = tid & 15;          // col group: cols tx*4 .. tx*4+3
    const int ty = tid >> 4;          // row group: rows ty*8 .. ty*8+7
    const size_t row0 = (size_t)blockIdx.x * 128;

    unsigned long long acc[4][4];     // [row-pair][col], packed over 2 rows
#pragma unroll
    for (int rp = 0; rp < 4; rp++)
#pragma unroll
        for (int c = 0; c < 4; c++) acc[rp][c] = 0ull;

    // loader mappings
    const int xrow = tid >> 1;              // 0..127 (2 threads per row)
    const int xk   = (tid & 1) * 16;        // k-half base
    const int wcol = tid >> 2;              // 0..63 (4 threads per col)
    const int wk   = (tid & 3) * 8;         // k-eighth base (2 float4)

#pragma unroll
    for (int kc = 0; kc < 4; kc++) {
        // --- load X tile k-major: Xt[k][row] ---
        {
            const float* xp = &X[(row0 + xrow) * DIN + kc * KCH + xk];
#pragma unroll
            for (int i = 0; i < 4; i++) {
                float4 v = *reinterpret_cast<const float4*>(xp + i * 4);
                const int k4 = xk + i * 4;
                Xt[k4 + 0][xrow] = v.x;
                Xt[k4 + 1][xrow] = v.y;
                Xt[k4 + 2][xrow] = v.z;
                Xt[k4 + 3][xrow] = v.w;
            }
        }
        // --- load W tile k-major, duplicated: Wt2[k][2c],[2c+1] = W[c][k] ---
        {
            const float* wp = &W[wcol * 144 + kc * KCH + wk];
#pragma unroll
            for (int i = 0; i < 2; i++) {
                float4 v = *reinterpret_cast<const float4*>(wp + i * 4);
                const int k4 = wk + i * 4;
                *reinterpret_cast<unsigned long long*>(&Wt2[k4 + 0][2 * wcol]) = pack2(v.x, v.x);
                *reinterpret_cast<unsigned long long*>(&Wt2[k4 + 1][2 * wcol]) = pack2(v.y, v.y);
                *reinterpret_cast<unsigned long long*>(&Wt2[k4 + 2][2 * wcol]) = pack2(v.z, v.z);
                *reinterpret_cast<unsigned long long*>(&Wt2[k4 + 3][2 * wcol]) = pack2(v.w, v.w);
            }
        }
        __syncthreads();

#pragma unroll
        for (int k = 0; k < KCH; k++) {
            ulonglong2 aa0 = *reinterpret_cast<ulonglong2*>(&Xt[k][ty * 8]);
            ulonglong2 aa1 = *reinterpret_cast<ulonglong2*>(&Xt[k][ty * 8 + 4]);
            ulonglong2 bb0 = *reinterpret_cast<ulonglong2*>(&Wt2[k][tx * 8]);
            ulonglong2 bb1 = *reinterpret_cast<ulonglong2*>(&Wt2[k][tx * 8 + 4]);
            acc[0][0] = ffma2(aa0.x, bb0.x, acc[0][0]);
            acc[0][1] = ffma2(aa0.x, bb0.y, acc[0][1]);
            acc[0][2] = ffma2(aa0.x, bb1.x, acc[0][2]);
            acc[0][3] = ffma2(aa0.x, bb1.y, acc[0][3]);
            acc[1][0] = ffma2(aa0.y, bb0.x, acc[1][0]);
            acc[1][1] = ffma2(aa0.y, bb0.y, acc[1][1]);
            acc[1][2] = ffma2(aa0.y, bb1.x, acc[1][2]);
            acc[1][3] = ffma2(aa0.y, bb1.y, acc[1][3]);
            acc[2][0] = ffma2(aa1.x, bb0.x, acc[2][0]);
            acc[2][1] = ffma2(aa1.x, bb0.y, acc[2][1]);
            acc[2][2] = ffma2(aa1.x, bb1.x, acc[2][2]);
            acc[2][3] = ffma2(aa1.x, bb1.y, acc[2][3]);
            acc[3][0] = ffma2(aa1.y, bb0.x, acc[3][0]);
            acc[3][1] = ffma2(aa1.y, bb0.y, acc[3][1]);
            acc[3][2] = ffma2(aa1.y, bb1.x, acc[3][2]);
            acc[3][3] = ffma2(aa1.y, bb1.y, acc[3][3]);
        }
        __syncthreads();
    }

    // --- store: each acc[rp][c] holds (row even, row odd) for col tx*4+c ---
#pragma unroll
    for (int rp = 0; rp < 4; rp++) {
        float2 p0 = unpack2(acc[rp][0]);
        float2 p1 = unpack2(acc[rp][1]);
        float2 p2 = unpack2(acc[rp][2]);
        float2 p3 = unpack2(acc[rp][3]);
        const size_t re = row0 + ty * 8 + 2 * rp;
        *reinterpret_cast<float4*>(&g_zx[re * NC + tx * 4]) =
            make_float4(p0.x, p1.x, p2.x, p3.x);
        *reinterpret_cast<float4*>(&g_zx[(re + 1) * NC + tx * 4]) =
            make_float4(p0.y, p1.y, p2.y, p3.y);
    }
}

// ---------------------------------------------------------------------------
// Kernel B: sequential recurrence. One warp per block, one block per batch row.
// Lanes 0-15  : gates 0 (forget) and 1 (input), qubit n = lane
// Lanes 16-31 : gates 2 (update) and 3 (output), qubit n = lane-16
// h broadcast via double-buffered smem (kills 16 of 26 SHFLs per step);
// sigmoid/tanh via hardware tanh.approx (1 MUFU each).
// ---------------------------------------------------------------------------
__global__ __launch_bounds__(32) void qlstm_recur(
    const float* __restrict__ W,      // [4,16,144]
    const float* __restrict__ bias,   // [4,16]
    const float* __restrict__ theta,  // [4,16]
    float* __restrict__ out)          // outputs [T,B,16] ++ hx [B,16] ++ cx [B,16]
{
    __shared__ float h_s[2][16];

    const int gw   = blockIdx.x;          // batch row
    const int lane = threadIdx.x;

    const int half = lane >> 4;
    const int n    = lane & 15;
    const int cA   = 32 * half + n;       // column of gate 2*half
    const int cB   = cA + 16;             // column of gate 2*half+1

    // recurrent weights, pre-packed as f32x2 pairs over j
    unsigned long long whA2[8], whB2[8];
#pragma unroll
    for (int j2 = 0; j2 < 8; j2++) {
        whA2[j2] = pack2(W[cA * 144 + 128 + 2 * j2], W[cA * 144 + 128 + 2 * j2 + 1]);
        whB2[j2] = pack2(W[cB * 144 + 128 + 2 * j2], W[cB * 144 + 128 + 2 * j2 + 1]);
    }
    const float ctA = bias[cA] + theta[cA];
    const float ctB = bias[cB] + theta[cB];

    // branch-free nonlinearity constants:
    //   half0 v0: sigmoid(x) = 0.5*tanh(0.5x)+0.5 ; half1 v0: tanh(x)
    const float s0 = half ? 1.0f : 0.5f;   // pre-scale (also the multiplier)
    const float b0 = half ? 0.0f : 0.5f;   // offset

    float h = 0.f, c = 0.f;
    if (lane < 16) h_s[0][n] = 0.f;
    __syncthreads();

    const float* zp = g_zx + (size_t)gw * NC;
    const size_t zstride = (size_t)BATCH * NC;

    // prefetch step 0
    float z0n = zp[cA];
    float z1n = zp[cB];

    float* outp = out + (size_t)gw * 16 + n;

    for (int t = 0; t < T_STEPS; t++) {
        // dot: h . Wh via broadcast LDS.64 + packed FFMA2
        unsigned long long accA = pack2(z0n + ctA, 0.f);
        unsigned long long accB = pack2(z1n + ctB, 0.f);
        const unsigned long long* hp =
            reinterpret_cast<const unsigned long long*>(h_s[t & 1]);
#pragma unroll
        for (int j2 = 0; j2 < 8; j2++) {
            unsigned long long hv = hp[j2];
            accA = ffma2(hv, whA2[j2], accA);
            accB = ffma2(hv, whB2[j2], accB);
        }
        float2 rA = unpack2(accA);
        float2 rB = unpack2(accB);
        float a0 = rA.x + rA.y;
        float a1 = rB.x + rB.y;

        // prefetch next step's pre-activations
        if (t + 1 < T_STEPS) {
            const float* q = zp + (size_t)(t + 1) * zstride;
            z0n = q[cA];
            z1n = q[cB];
        }

        a0 = __cosf(a0);
        a1 = __cosf(a1);

        // inclusive prefix product (cumprod over qubits) within each half-warp
#pragma unroll
        for (int d = 1; d < 16; d <<= 1) {
            float p0 = __shfl_up_sync(0xffffffffu, a0, d, 16);
            float p1 = __shfl_up_sync(0xffffffffu, a1, d, 16);
            if (n >= d) { a0 *= p0; a1 *= p1; }
        }

        // gate nonlinearities (1 MUFU each)
        float v0 = fmaf(s0, tanh_apx(a0 * s0), b0);               // sig | tanh
        float v1 = fmaf(0.5f, tanh_apx(a1 * 0.5f), 0.5f);         // sigmoid

        // exchange with partner half-warp lane
        float pv0 = __shfl_sync(0xffffffffu, v0, lane ^ 16);
        float pv1 = __shfl_sync(0xffffffffu, v1, lane ^ 16);

        float f_ = half ? pv0 : v0;
        float i_ = half ? pv1 : v1;
        float g_ = half ? v0  : pv0;
        float o_ = half ? v1  : pv1;

        c = fmaf(f_, c, i_ * g_);
        h = o_ * tanh_apx(c);

        if (half == 0) {
            outp[(size_t)t * (BATCH * 16)] = h;
            h_s[(t + 1) & 1][n] = h;       // publish h for next step's dot
        }
        __syncthreads();                    // BAR nw=1: ~3 cyc, drains STS
    }

    if (half == 0) {
        const size_t base = (size_t)T_STEPS * BATCH * 16;
        out[base + (size_t)gw * 16 + n] = h;                       // hx
        out[base + (size_t)BATCH * 16 + (size_t)gw * 16 + n] = c;  // cx
    }
}

// ---------------------------------------------------------------------------
extern "C" void kernel_launch(void* const* d_in, const int* in_sizes, int n_in,
                              void* d_out, int out_size) {
    const float* X     = (const float*)d_in[0];   // [T,B,128]
    const float* W     = (const float*)d_in[1];   // [4,16,144]
    const float* bias  = (const float*)d_in[2];   // [4,16]
    const float* theta = (const float*)d_in[3];   // [4,16]
    float* out = (float*)d_out;

    // Kernel A: 524288 rows / 128 per block
    qlstm_gemm_x<<<(T_STEPS * BATCH) / 128, 256>>>(X, W);

    // Kernel B: one warp per batch row, one block per warp (load balance)
    qlstm_recur<<<BATCH, 32>>>(W, bias, theta, out);
}

// round 17
// speedup vs baseline: 1.3638x; 1.3611x over previous
#include <cuda_runtime.h>
#include <math.h>

#define T_STEPS 256
#define BATCH   2048
#define DIN     128
#define NQ      16
#define NC      64   // 4 gates * 16 qubits

// 134 MB scratch for the precomputed x-part of the pre-activations.
// zx[t*BATCH*NC + b*NC + c] = sum_{d<128} x[t,b,d] * W[c,d]
__device__ float g_zx[(size_t)T_STEPS * BATCH * NC];

// ---------------------------------------------------------------------------
// Packed fp32x2 helpers (sm_100+ PTX; ptxas will not auto-fuse these)
// ---------------------------------------------------------------------------
__device__ __forceinline__ unsigned long long ffma2(
    unsigned long long a, unsigned long long b, unsigned long long c) {
    unsigned long long d;
    asm("fma.rn.f32x2 %0, %1, %2, %3;" : "=l"(d) : "l"(a), "l"(b), "l"(c));
    return d;
}
__device__ __forceinline__ unsigned long long dup2(float x) {
    unsigned long long d;
    asm("mov.b64 %0, {%1, %1};" : "=l"(d) : "f"(x));
    return d;
}
__device__ __forceinline__ unsigned long long pack2(float lo, float hi) {
    unsigned long long d;
    asm("mov.b64 %0, {%1, %2};" : "=l"(d) : "f"(lo), "f"(hi));
    return d;
}
__device__ __forceinline__ float2 unpack2(unsigned long long v) {
    float2 r;
    asm("mov.b64 {%0, %1}, %2;" : "=f"(r.x), "=f"(r.y) : "l"(v));
    return r;
}
__device__ __forceinline__ float tanh_apx(float x) {
    float r;
    asm("tanh.approx.f32 %0, %1;" : "=f"(r) : "f"(x));
    return r;
}

// ---------------------------------------------------------------------------
// Kernel A (reverted to the proven R11 version, 229us):
// GEMM. M = T*B = 524288 rows, N = 64, K = 128 (2 chunks of 64).
// Both tiles stored k-major in smem: inner loop = 2x LDS.128 + 8 FFMA2.
// Thread computes a 4x4 register tile as 4x2 packed f32x2.
// ---------------------------------------------------------------------------
__global__ __launch_bounds__(256) void qlstm_gemm_x(
    const float* __restrict__ X,   // [M, 128]
    const float* __restrict__ W)   // [64, 144] (only d<128 used here)
{
    __shared__ float Xt[64][68];   // [k][row]
    __shared__ float Wt[64][68];   // [k][col]

    const int tid = threadIdx.x;
    const int tx = tid & 15;        // col group (4 cols -> 2 packed pairs)
    const int ty = tid >> 4;        // row group (4 rows)
    const size_t row0 = (size_t)blockIdx.x * 64;

    // loader mapping: 4 threads per row/col along k
    const int lrow = tid >> 2;            // 0..63
    const int lkq  = (tid & 3) * 4;       // 0,4,8,12

    unsigned long long acc[4][2];
#pragma unroll
    for (int r = 0; r < 4; r++) { acc[r][0] = 0ull; acc[r][1] = 0ull; }

#pragma unroll
    for (int kc = 0; kc < 2; kc++) {
        // --- load X tile k-major: Xt[k][row] ---
        {
            const float* xp = &X[(row0 + lrow) * DIN + kc * 64];
#pragma unroll
            for (int i = 0; i < 4; i++) {
                int k4 = lkq + i * 16;
                float4 v = *reinterpret_cast<const float4*>(xp + k4);
                Xt[k4 + 0][lrow] = v.x;
                Xt[k4 + 1][lrow] = v.y;
                Xt[k4 + 2][lrow] = v.z;
                Xt[k4 + 3][lrow] = v.w;
            }
        }
        // --- load W tile k-major: Wt[k][col] ---
        {
            const float* wp = &W[lrow * 144 + kc * 64];
#pragma unroll
            for (int i = 0; i < 4; i++) {
                int k4 = lkq + i * 16;
                float4 v = *reinterpret_cast<const float4*>(wp + k4);
                Wt[k4 + 0][lrow] = v.x;
                Wt[k4 + 1][lrow] = v.y;
                Wt[k4 + 2][lrow] = v.z;
                Wt[k4 + 3][lrow] = v.w;
            }
        }
        __syncthreads();

#pragma unroll 16
        for (int k = 0; k < 64; k++) {
            ulonglong2 bb = *reinterpret_cast<ulonglong2*>(&Wt[k][tx * 4]);
            float4 av = *reinterpret_cast<float4*>(&Xt[k][ty * 4]);
            unsigned long long a0 = dup2(av.x);
            unsigned long long a1 = dup2(av.y);
            unsigned long long a2 = dup2(av.z);
            unsigned long long a3 = dup2(av.w);
            acc[0][0] = ffma2(a0, bb.x, acc[0][0]);
            acc[0][1] = ffma2(a0, bb.y, acc[0][1]);
            acc[1][0] = ffma2(a1, bb.x, acc[1][0]);
            acc[1][1] = ffma2(a1, bb.y, acc[1][1]);
            acc[2][0] = ffma2(a2, bb.x, acc[2][0]);
            acc[2][1] = ffma2(a2, bb.y, acc[2][1]);
            acc[3][0] = ffma2(a3, bb.x, acc[3][0]);
            acc[3][1] = ffma2(a3, bb.y, acc[3][1]);
        }
        __syncthreads();
    }

    // --- store 4x4 tile, float4 per row ---
#pragma unroll
    for (int r = 0; r < 4; r++) {
        float2 lo = unpack2(acc[r][0]);
        float2 hi = unpack2(acc[r][1]);
        float4 v = make_float4(lo.x, lo.y, hi.x, hi.y);
        *reinterpret_cast<float4*>(
            &g_zx[(row0 + ty * 4 + r) * NC + tx * 4]) = v;
    }
}

// ---------------------------------------------------------------------------
// Kernel B: sequential recurrence. TWO warps per batch row (64 threads),
// one gate-column per lane: col = tid (0-15 f, 16-31 i, 32-47 g, 48-63 o).
// Doubles resident warps/SM (20.6% -> 43% occ) to hide the per-step latency
// chain. Cross-warp exchange via double-buffered smem + 2 syncthreads/step.
// All 64 lanes redundantly compute (c, h) for qubit n = lane&15.
// ---------------------------------------------------------------------------
__global__ __launch_bounds__(64) void qlstm_recur(
    const float* __restrict__ W,      // [4,16,144]
    const float* __restrict__ bias,   // [4,16]
    const float* __restrict__ theta,  // [4,16]
    float* __restrict__ out)          // outputs [T,B,16] ++ hx [B,16] ++ cx [B,16]
{
    __shared__ float h_s[2][16];      // h(t) broadcast, double-buffered
    __shared__ float v_s[2][64];      // gate values exchange, double-buffered

    const int gw  = blockIdx.x;       // batch row
    const int tid = threadIdx.x;      // == gate column c (0..63)
    const int n   = tid & 15;         // qubit index
    const int gate = tid >> 4;        // 0=f, 1=i, 2=g, 3=o

    // recurrent weights for this column, pre-packed as f32x2 pairs over j
    unsigned long long wh2[8];
#pragma unroll
    for (int j2 = 0; j2 < 8; j2++)
        wh2[j2] = pack2(W[tid * 144 + 128 + 2 * j2], W[tid * 144 + 128 + 2 * j2 + 1]);
    const float ct = bias[tid] + theta[tid];

    // branch-free nonlinearity constants: tanh for gate 2, sigmoid otherwise
    //   sigmoid(x) = 0.5*tanh(0.5x) + 0.5
    const float s0 = (gate == 2) ? 1.0f : 0.5f;
    const float b0 = (gate == 2) ? 0.0f : 0.5f;

    float h = 0.f, c = 0.f;
    if (tid < 16) h_s[0][n] = 0.f;
    __syncthreads();

    const float*  zp      = g_zx + (size_t)gw * NC + tid;
    const size_t  zstride = (size_t)BATCH * NC;

    // prefetch depth 2
    float za = zp[0];
    float zb = zp[zstride];

    float* outp = out + (size_t)gw * 16 + n;

    for (int t = 0; t < T_STEPS; t++) {
        const int p = t & 1;

        // --- dot: a = z + ct + h(t) . Wh  (h from smem, packed FFMA2) ---
        ulonglong2 h01 = *reinterpret_cast<const ulonglong2*>(&h_s[p][0]);
        ulonglong2 h23 = *reinterpret_cast<const ulonglong2*>(&h_s[p][4]);
        ulonglong2 h45 = *reinterpret_cast<const ulonglong2*>(&h_s[p][8]);
        ulonglong2 h67 = *reinterpret_cast<const ulonglong2*>(&h_s[p][12]);
        unsigned long long accA = pack2(za + ct, 0.f);
        unsigned long long accB = 0ull;
        accA = ffma2(h01.x, wh2[0], accA);
        accB = ffma2(h01.y, wh2[1], accB);
        accA = ffma2(h23.x, wh2[2], accA);
        accB = ffma2(h23.y, wh2[3], accB);
        accA = ffma2(h45.x, wh2[4], accA);
        accB = ffma2(h45.y, wh2[5], accB);
        accA = ffma2(h67.x, wh2[6], accA);
        accB = ffma2(h67.y, wh2[7], accB);
        float2 rA = unpack2(accA);
        float2 rB = unpack2(accB);
        float a = (rA.x + rB.x) + (rA.y + rB.y);

        // advance the z prefetch pipeline (depth 2)
        za = zb;
        if (t + 2 < T_STEPS) zb = zp[(size_t)(t + 2) * zstride];

        a = __cosf(a);

        // inclusive prefix product (cumprod over qubits) within the half-warp
#pragma unroll
        for (int d = 1; d < 16; d <<= 1) {
            float pp = __shfl_up_sync(0xffffffffu, a, d, 16);
            if (n >= d) a *= pp;
        }

        // gate nonlinearity (1 MUFU)
        float v = fmaf(s0, tanh_apx(a * s0), b0);

        // exchange gate values across the two warps
        v_s[p][tid] = v;
        __syncthreads();

        float f_ = v_s[p][n];
        float i_ = v_s[p][16 + n];
        float g_ = v_s[p][32 + n];
        float o_ = v_s[p][48 + n];

        c = fmaf(f_, c, i_ * g_);
        h = o_ * tanh_apx(c);

        if (tid < 16) {
            outp[(size_t)t * (BATCH * 16)] = h;
            h_s[1 - p][n] = h;             // publish h(t+1)
        }
        __syncthreads();
    }

    if (tid < 16) {
        const size_t base = (size_t)T_STEPS * BATCH * 16;
        out[base + (size_t)gw * 16 + n] = h;                       // hx
        out[base + (size_t)BATCH * 16 + (size_t)gw * 16 + n] = c;  // cx
    }
}

// ---------------------------------------------------------------------------
extern "C" void kernel_launch(void* const* d_in, const int* in_sizes, int n_in,
                              void* d_out, int out_size) {
    const float* X     = (const float*)d_in[0];   // [T,B,128]
    const float* W     = (const float*)d_in[1];   // [4,16,144]
    const float* bias  = (const float*)d_in[2];   // [4,16]
    const float* theta = (const float*)d_in[3];   // [4,16]
    float* out = (float*)d_out;

    // Kernel A: 524288 rows / 64 per block
    qlstm_gemm_x<<<(T_STEPS * BATCH) / 64, 256>>>(X, W);

    // Kernel B: two warps per batch row, one block per row
    qlstm_recur<<<BATCH, 64>>>(W, bias, theta, out);
}